// round 11
// baseline (speedup 1.0000x reference)
#include <cuda_runtime.h>

// Problem constants
#define B_    2
#define C_    128
#define T_    4
#define S_    16384      // T*H*W
#define NH_   32
#define N_    1024       // T*h*w = 4*16*16
#define TABSZ 6727       // (2T-1)*(2h-1)*(2w-1) = 7*31*31
#define EPS_  1e-5f
#define LOG2E_ 1.4426950408889634f

// ---------------- scratch (static device globals; no runtime alloc) -------
__device__ float g_stat[3][B_][32][2];      // groupnorm sum / sumsq partials
__device__ float g_aff[3][B_][C_][2];       // per-channel affine (a, b)
__device__ float g_qp[B_][NH_][N_][4];      // pooled Q raw sums
__device__ float g_kp[B_][NH_][N_][4];      // pooled K raw sums
__device__ float g_vp[B_][NH_][N_][64];     // RAW V, tf32-rounded, vp layout

// ---------------- tf32 / mma helpers ---------------------------------------
__device__ __forceinline__ unsigned tf32r(float f) {
    unsigned u; asm("cvt.rna.tf32.f32 %0, %1;" : "=r"(u) : "f"(f)); return u;
}
__device__ __forceinline__ void mma_tf32(float* d, unsigned a0, unsigned a1,
                                         unsigned a2, unsigned a3,
                                         unsigned b0, unsigned b1) {
    asm("mma.sync.aligned.m16n8k8.row.col.f32.tf32.tf32.f32 "
        "{%0,%1,%2,%3}, {%4,%5,%6,%7}, {%8,%9}, {%0,%1,%2,%3};"
        : "+f"(d[0]), "+f"(d[1]), "+f"(d[2]), "+f"(d[3])
        : "r"(a0), "r"(a1), "r"(a2), "r"(a3), "r"(b0), "r"(b1));
}
// split fp32 into tf32-hi (masked bits) + exact fp32 residual
__device__ __forceinline__ void split32(float f, unsigned& hi, unsigned& lo) {
    unsigned u = __float_as_uint(f);
    hi = u & 0xFFFFE000u;
    lo = __float_as_uint(f - __uint_as_float(hi));
}
__device__ __forceinline__ float ex2f(float x) {
    float y; asm("ex2.approx.ftz.f32 %0, %1;" : "=f"(y) : "f"(x)); return y;
}

// ---------------- cp.async helpers ----------------------------------------
__device__ __forceinline__ void cp16(void* smem, const void* g) {
    unsigned sa = (unsigned)__cvta_generic_to_shared(smem);
    asm volatile("cp.async.cg.shared.global [%0], [%1], 16;" :: "r"(sa), "l"(g));
}
__device__ __forceinline__ void cp_commit() {
    asm volatile("cp.async.commit_group;");
}
__device__ __forceinline__ void cp_wait0() {
    asm volatile("cp.async.wait_group 0;" ::: "memory");
}
__device__ __forceinline__ void cp_wait1() {
    asm volatile("cp.async.wait_group 1;" ::: "memory");
}

// ================= K0: zero accumulators ===================================
__global__ void zero_kernel() {      // <<<512, 256>>>
    int idx = blockIdx.x * 256 + threadIdx.x;       // 0..131071
    float4 z = make_float4(0.f, 0.f, 0.f, 0.f);
    if (idx < 65536) ((float4*)g_qp)[idx] = z;
    else             ((float4*)g_kp)[idx - 65536] = z;
    if (idx < 96)    ((float4*)g_stat)[idx] = z;
}

// ================= K1: projections via 3xTF32 tensor-core GEMM =============
#define WS_PITCH 36
#define XS_PITCH 72
#define WS_STAGE (128 * WS_PITCH)     // 4608 floats
#define XS_STAGE (32 * XS_PITCH)      // 2304 floats
#define SB_OFF   (2 * WS_STAGE + 2 * XS_STAGE)
#define PROJ_SMEM_FLOATS (SB_OFF + 512)
#define PROJ_SMEM_BYTES  (PROJ_SMEM_FLOATS * 4)

__global__ __launch_bounds__(256, 2) void proj_kernel(
    const float* __restrict__ x, const float* __restrict__ Wq,
    const float* __restrict__ Wk, const float* __restrict__ Wv) {
    extern __shared__ float sm[];
    float* Ws   = sm;
    float* Xs   = sm + 2 * WS_STAGE;
    float* sbuf = sm + SB_OFF;

    const int pr = blockIdx.z;
    const float* Wsel = (pr == 0) ? Wq : ((pr == 1) ? Wk : Wv);
    const int b   = blockIdx.y;
    const int s_t = blockIdx.x << 6;
    const int tid = threadIdx.x;
    const float* xb = x + (size_t)b * C_ * S_;

    auto issue = [&](int kc, int st) {
        float* wd = Ws + st * WS_STAGE;
        float* xd = Xs + st * XS_STAGE;
#pragma unroll
        for (int j = 0; j < 4; j++) {
            int e = tid + 256 * j;
            int o = e >> 3, seg = e & 7;
            cp16(wd + o * WS_PITCH + seg * 4, Wsel + o * 128 + kc * 32 + seg * 4);
        }
#pragma unroll
        for (int j = 0; j < 2; j++) {
            int e = tid + 256 * j;
            int c = e >> 4, seg = e & 15;
            cp16(xd + c * XS_PITCH + seg * 4,
                 xb + (size_t)(kc * 32 + c) * S_ + s_t + seg * 4);
        }
        cp_commit();
    };

    const int warp = tid >> 5, lane = tid & 31;
    const int gid = lane >> 2, tg = lane & 3;
    const int ow = warp >> 1, sw = warp & 1;
    const int o0 = ow << 5;
    const int sbase = sw << 5;

    float acc[2][4][4];
#pragma unroll
    for (int mb = 0; mb < 2; mb++)
#pragma unroll
        for (int nb = 0; nb < 4; nb++)
#pragma unroll
            for (int i = 0; i < 4; i++) acc[mb][nb][i] = 0.f;

    issue(0, 0);
    for (int kc = 0; kc < 4; kc++) {
        cp_wait0();
        __syncthreads();
        if (kc < 3) issue(kc + 1, (kc + 1) & 1);
        const float* Wb = Ws + (kc & 1) * WS_STAGE;
        const float* Xb = Xs + (kc & 1) * XS_STAGE;

#pragma unroll
        for (int ks = 0; ks < 4; ks++) {
            unsigned bh[4][2], bl[4][2];
#pragma unroll
            for (int nb = 0; nb < 4; nb++) {
                const float* xp = Xb + (ks * 8 + tg) * XS_PITCH
                                + sbase + nb * 8 + gid;
                split32(xp[0],            bh[nb][0], bl[nb][0]);
                split32(xp[4 * XS_PITCH], bh[nb][1], bl[nb][1]);
            }
#pragma unroll
            for (int mb = 0; mb < 2; mb++) {
                const float* wp0 = Wb + (o0 + mb * 16 + gid) * WS_PITCH
                                 + ks * 8 + tg;
                const float* wp1 = wp0 + 8 * WS_PITCH;
                unsigned ah0, ah1, ah2, ah3, al0, al1, al2, al3;
                split32(wp0[0], ah0, al0);
                split32(wp1[0], ah1, al1);
                split32(wp0[4], ah2, al2);
                split32(wp1[4], ah3, al3);
#pragma unroll
                for (int nb = 0; nb < 4; nb++) {
                    mma_tf32(acc[mb][nb], ah0, ah1, ah2, ah3, bh[nb][0], bh[nb][1]);
                    mma_tf32(acc[mb][nb], ah0, ah1, ah2, ah3, bl[nb][0], bl[nb][1]);
                    mma_tf32(acc[mb][nb], al0, al1, al2, al3, bh[nb][0], bh[nb][1]);
                }
            }
        }
        __syncthreads();
    }

    // ---- epilogue coordinates
    const int t  = s_t >> 12;
    const int hh = (s_t >> 6) & 63;
    const int y  = hh >> 2, sy = hh & 3;
    const int nbase = t * 256 + (y << 4);

    if (pr < 2) {
        float* dstp = (pr == 0) ? &g_qp[0][0][0][0] : &g_kp[0][0][0][0];
#pragma unroll
        for (int mb = 0; mb < 2; mb++) {
            const int cA = o0 + mb * 16 + gid, cB = cA + 8;
#pragma unroll
            for (int nb = 0; nb < 4; nb++) {
                float sA = acc[mb][nb][0] + acc[mb][nb][1];
                float sB = acc[mb][nb][2] + acc[mb][nb][3];
                sA += __shfl_xor_sync(0xffffffffu, sA, 1);
                sB += __shfl_xor_sync(0xffffffffu, sB, 1);
                if ((tg & 1) == 0) {
                    int n = nbase + (sw << 3) + (nb << 1) + (tg >> 1);
                    atomicAdd(dstp + (((size_t)(b * 32 + (cA >> 2)) * 1024 + n) << 2)
                                   + (cA & 3), sA);
                    atomicAdd(dstp + (((size_t)(b * 32 + (cB >> 2)) * 1024 + n) << 2)
                                   + (cB & 3), sB);
                }
            }
        }
    } else {
        float* Zs = sm;                      // 128 x 72 = 9216 < 2*WS_STAGE
#pragma unroll
        for (int mb = 0; mb < 2; mb++) {
            const int r = o0 + mb * 16 + gid;
#pragma unroll
            for (int nb = 0; nb < 4; nb++) {
                int col = sbase + nb * 8 + (tg << 1);
                *(float2*)&Zs[r * 72 + col]       = make_float2(acc[mb][nb][0], acc[mb][nb][1]);
                *(float2*)&Zs[(r + 8) * 72 + col] = make_float2(acc[mb][nb][2], acc[mb][nb][3]);
            }
        }
    }

    // ---- fused GroupNorm partial stats
#pragma unroll
    for (int mb = 0; mb < 2; mb++)
#pragma unroll
        for (int hi = 0; hi < 2; hi++) {
            float s = 0.f, s2 = 0.f;
#pragma unroll
            for (int nb = 0; nb < 4; nb++) {
                float v0 = acc[mb][nb][hi * 2 + 0];
                float v1 = acc[mb][nb][hi * 2 + 1];
                s += v0 + v1;
                s2 = fmaf(v0, v0, s2); s2 = fmaf(v1, v1, s2);
            }
            s  += __shfl_xor_sync(0xffffffffu, s, 1);
            s  += __shfl_xor_sync(0xffffffffu, s, 2);
            s2 += __shfl_xor_sync(0xffffffffu, s2, 1);
            s2 += __shfl_xor_sync(0xffffffffu, s2, 2);
            if (tg == 0) {
                int idx = (((warp << 3) | gid) << 3) | (mb << 2) | (hi << 1);
                sbuf[idx]     = s;
                sbuf[idx + 1] = s2;
            }
        }
    __syncthreads();

    if (pr == 2) {
        const float* Zs = sm;
#pragma unroll
        for (int j = 0; j < 8; j++) {
            int e = tid + (j << 8);
            int c = e >> 4, xq = e & 15;
            float4 v = *(const float4*)&Zs[c * 72 + (xq << 2)];
            float4 r = make_float4(
                __uint_as_float(tf32r(v.x)), __uint_as_float(tf32r(v.y)),
                __uint_as_float(tf32r(v.z)), __uint_as_float(tf32r(v.w)));
            *(float4*)&g_vp[b][c >> 2][nbase + xq][((c & 3) << 4) + (sy << 2)] = r;
        }
    }
    if (tid < 64) {
        int grp = tid >> 1, v = tid & 1;
        float tot = 0.f;
#pragma unroll
        for (int ci = 0; ci < 4; ci++) {
            int ch = (grp << 2) + ci;
            int cow = ch >> 5, r = ch & 31;
            int cmb = r >> 4, chi = (r >> 3) & 1, cgid = r & 7;
#pragma unroll
            for (int csw = 0; csw < 2; csw++) {
                int w2 = (cow << 1) | csw;
                tot += sbuf[(((w2 << 3) | cgid) << 3) | (cmb << 2) | (chi << 1) | v];
            }
        }
        atomicAdd(&g_stat[pr][b][grp][v], tot);
    }
}

// ================= K2: finalize stats -> per-channel affine ================
__global__ void finalize_stats(
    const float* __restrict__ gqg, const float* __restrict__ gqb,
    const float* __restrict__ gkg, const float* __restrict__ gkb,
    const float* __restrict__ gvg, const float* __restrict__ gvb) {   // <<<1,192>>>
    int i = threadIdx.x;
    int pr = i >> 6, r = i & 63, b = r >> 5, grp = r & 31;
    float s  = g_stat[pr][b][grp][0];
    float s2 = g_stat[pr][b][grp][1];
    float mean = s * (1.f / 65536.f);
    float var  = s2 * (1.f / 65536.f) - mean * mean;
    float rstd = rsqrtf(var + EPS_);
    const float* ga = (pr == 0) ? gqg : ((pr == 1) ? gkg : gvg);
    const float* be = (pr == 0) ? gqb : ((pr == 1) ? gkb : gvb);
#pragma unroll
    for (int d = 0; d < 4; d++) {
        int c = (grp << 2) + d;
        float a = rstd * ga[c];
        g_aff[pr][b][c][0] = a;
        g_aff[pr][b][c][1] = be[c] - mean * a;
    }
}

// ================= K3: fused tensor-core patch attention ===================
// CTA = (b, head, PAIR of 128-row tiles): tab/K/kc/maxima loaded once, two
// sequential mainloops. grid (4, 32, 2) = 256 CTAs -> single wave.
// INTERLEAVED n-block convention: block j = cols {8n + j}. Thread n=gid
// loads contiguous logical cols 8gid..8gid+7 per key row via 2x LDS.128,
// with per-row column rotation f(r)=4*(r&1)+16*((r>>1)&1) words for
// conflict-free banks. D-frags: thread owns cols 16tg..16tg+15
// (acc[j][0]->pixel j, acc[j][1]->pixel 8+j, channel dd = tg) -> coalesced
// float4 epilogue (round-8 mapping, now with conflict-free loads).
#define VSP_    64
#define VS_BUF  (64 * VSP_)                 // 4096 floats per stage
#define SM_TAB  0
#define SM_K    6728                        // 1024 float4
#define SM_KC   (SM_K + 4096)               // 1024 ints
#define SM_VS   (SM_KC + 1024)              // 3 * 4096
#define SM_RED  (SM_VS + 3 * VS_BUF)        // 16
#define ATTN_SMEM_FLOATS (SM_RED + 16)
#define ATTN_SMEM_BYTES (ATTN_SMEM_FLOATS * 4)

__global__ __launch_bounds__(256, 2) void attn_kernel(
    const float* __restrict__ rel_table, float* __restrict__ out) {
    extern __shared__ float sm[];
    float*  tab  = sm + SM_TAB;
    float4* ks4  = (float4*)(sm + SM_K);
    int*    kc   = (int*)(sm + SM_KC);
    float*  vsb0 = sm + SM_VS;
    float*  red  = sm + SM_RED;

    const int b = blockIdx.z, g = blockIdx.y;
    const int tid = threadIdx.x;

    // V writer lambda: 16B chunks with per-row column rotation
    auto kickV = [&](int chunk, int stage) {
        const float* vsrc = &g_vp[b][g][chunk << 6][0];
        float* vdst = vsb0 + stage * VS_BUF;
#pragma unroll
        for (int j = 0; j < 4; j++) {
            int idx = tid + 256 * j;
            int row = idx >> 4, seg = idx & 15;
            int pcol = ((seg << 2) + ((row & 1) << 2) + ((row & 2) << 3)) & 63;
            cp16(vdst + row * VSP_ + pcol, vsrc + row * 64 + (seg << 2));
        }
        cp_commit();
    };

    // ---- kick off V chunks 0 and 1 immediately (V is tile-independent)
    kickV(0, 0);
    kickV(1, 1);

    // ---- load bias table (scaled by log2e), normalized K; reduce maxima
    float tmax = -1e30f;
    for (int i = tid; i < TABSZ; i += 256) {
        float v = rel_table[g * TABSZ + i] * LOG2E_;
        tab[i] = v;
        tmax = fmaxf(tmax, v);
    }
    const float* afk = &g_aff[1][b][g << 2][0];     // [a0,b0,a1,b1,a2,b2,a3,b3]
    float4 afk0 = *(const float4*)afk;
    float4 afk1 = *(const float4*)(afk + 4);
    float knmax = 0.f;
    for (int i = tid; i < 1024; i += 256) {
        float4 kr = *(const float4*)&g_kp[b][g][i][0];
        float4 kk;
        kk.x = fmaf(kr.x * 0.0625f, afk0.x, afk0.y);
        kk.y = fmaf(kr.y * 0.0625f, afk0.z, afk0.w);
        kk.z = fmaf(kr.z * 0.0625f, afk1.x, afk1.y);
        kk.w = fmaf(kr.w * 0.0625f, afk1.z, afk1.w);
        ks4[i] = kk;
        kc[i]  = 961 * (i >> 8) + 31 * ((i >> 4) & 15) + (i & 15);
        float nn = fmaf(kk.x, kk.x, fmaf(kk.y, kk.y, fmaf(kk.z, kk.z, kk.w * kk.w)));
        knmax = fmaxf(knmax, nn);
    }
#pragma unroll
    for (int o = 16; o; o >>= 1) {
        tmax  = fmaxf(tmax,  __shfl_xor_sync(0xffffffffu, tmax,  o));
        knmax = fmaxf(knmax, __shfl_xor_sync(0xffffffffu, knmax, o));
    }
    int w = tid >> 5;
    if ((tid & 31) == 0) { red[w] = tmax; red[8 + w] = knmax; }
    __syncthreads();
    tmax = red[0]; knmax = red[8];
#pragma unroll
    for (int i = 1; i < 8; i++) {
        tmax = fmaxf(tmax, red[i]); knmax = fmaxf(knmax, red[8 + i]);
    }
    const float kn = sqrtf(knmax);

    // ---- tile-invariant per-thread identity
    const int warp = tid >> 5, lane = tid & 31;
    const int gid = lane >> 2, tg = lane & 3;
    const int frot = ((tg & 1) << 2) | ((tg & 2) << 3);
    const int p0v = ((gid << 3) + frot) & 63;
    const int p1v = (p0v + 4) & 63;
    const float* afq = &g_aff[0][b][g << 2][0];
    const float4 afq0 = *(const float4*)afq;
    const float4 afq1 = *(const float4*)(afq + 4);
    const float HS = 0.5f * LOG2E_;
    // epilogue: this thread owns channel dd = tg only (cols 16tg..16tg+15)
    const float aA = g_aff[2][b][(g << 2) + tg][0];
    const float aB = g_aff[2][b][(g << 2) + tg][1];

    for (int it = 0; it < 2; it++) {
        const int n0 = ((blockIdx.x << 1) | it) << 7;
        if (it) {
            __syncthreads();        // all warps done reading tile-0's V ring
            kickV(0, 0);
            kickV(1, 1);
        }

        // ---- per-tile q: normalize then scale to log2 domain
        const int r0 = (warp << 4) + gid;
        const int nq0 = n0 + r0, nq1 = nq0 + 8;
        float4 qr0 = *(const float4*)&g_qp[b][g][nq0][0];
        float4 qr1 = *(const float4*)&g_qp[b][g][nq1][0];
        float4 q0, q1;
        q0.x = fmaf(qr0.x * 0.0625f, afq0.x, afq0.y) * HS;
        q0.y = fmaf(qr0.y * 0.0625f, afq0.z, afq0.w) * HS;
        q0.z = fmaf(qr0.z * 0.0625f, afq1.x, afq1.y) * HS;
        q0.w = fmaf(qr0.w * 0.0625f, afq1.z, afq1.w) * HS;
        q1.x = fmaf(qr1.x * 0.0625f, afq0.x, afq0.y) * HS;
        q1.y = fmaf(qr1.y * 0.0625f, afq0.z, afq0.w) * HS;
        q1.z = fmaf(qr1.z * 0.0625f, afq1.x, afq1.y) * HS;
        q1.w = fmaf(qr1.w * 0.0625f, afq1.z, afq1.w) * HS;
        const float qq0 = fmaf(q0.x, q0.x, fmaf(q0.y, q0.y, fmaf(q0.z, q0.z, q0.w * q0.w)));
        const float qq1 = fmaf(q1.x, q1.x, fmaf(q1.y, q1.y, fmaf(q1.z, q1.z, q1.w * q1.w)));
        const float bnd0 = fmaf(sqrtf(qq0), kn, tmax);
        const float bnd1 = fmaf(sqrtf(qq1), kn, tmax);
        const int cn0 = 961 * (nq0 >> 8) + 31 * ((nq0 >> 4) & 15) + (nq0 & 15) + 3363;
        const int cn1 = 961 * (nq1 >> 8) + 31 * ((nq1 >> 4) & 15) + (nq1 & 15) + 3363;

        float acc[8][4];
#pragma unroll
        for (int j = 0; j < 8; j++)
#pragma unroll
            for (int i = 0; i < 4; i++) acc[j][i] = 0.f;
        float wsum0 = 0.f, wsum1 = 0.f;

        // ---- main loop: 16 chunks of 64 keys, 3-stage cp.async ring
        for (int mc = 0; mc < 16; mc++) {
            if (mc < 15) cp_wait1(); else cp_wait0();
            __syncthreads();
            if (mc + 2 < 16) kickV(mc + 2, (mc + 2) % 3);
            const float* vsb = vsb0 + (mc % 3) * VS_BUF;
            const int m0 = mc << 6;

#pragma unroll
            for (int sub = 0; sub < 8; sub++) {
                const int mk = m0 + (sub << 3);
                float4 k0 = ks4[mk + tg];
                float4 k1 = ks4[mk + tg + 4];
                int c0i = kc[mk + tg], c1i = kc[mk + tg + 4];

                float d00 = fmaf(q0.x, k0.x, fmaf(q0.y, k0.y, fmaf(q0.z, k0.z, q0.w * k0.w)));
                float d01 = fmaf(q0.x, k1.x, fmaf(q0.y, k1.y, fmaf(q0.z, k1.z, q0.w * k1.w)));
                float d10 = fmaf(q1.x, k0.x, fmaf(q1.y, k0.y, fmaf(q1.z, k0.z, q1.w * k0.w)));
                float d11 = fmaf(q1.x, k1.x, fmaf(q1.y, k1.y, fmaf(q1.z, k1.z, q1.w * k1.w)));

                float w00 = ex2f(d00 + tab[cn0 - c0i] - bnd0);
                float w01 = ex2f(d01 + tab[cn0 - c1i] - bnd0);
                float w10 = ex2f(d10 + tab[cn1 - c0i] - bnd1);
                float w11 = ex2f(d11 + tab[cn1 - c1i] - bnd1);
                wsum0 += w00 + w01;
                wsum1 += w10 + w11;

                unsigned a0 = __float_as_uint(w00), a1 = __float_as_uint(w10);
                unsigned a2 = __float_as_uint(w01), a3 = __float_as_uint(w11);

                // vectorized B-frags: logical cols 8gid..8gid+7 of key rows
                // mk+tg and mk+tg+4 -> blocks j=0..7 at n=gid (interleaved)
                const float* vrow0 = vsb + ((sub << 3) + tg) * VSP_;
                const float* vrow1 = vrow0 + 4 * VSP_;
                float4 x0 = *(const float4*)(vrow0 + p0v);
                float4 x1 = *(const float4*)(vrow0 + p1v);
                float4 y0 = *(const float4*)(vrow1 + p0v);
                float4 y1 = *(const float4*)(vrow1 + p1v);
                mma_tf32(acc[0], a0, a1, a2, a3, __float_as_uint(x0.x), __float_as_uint(y0.x));
                mma_tf32(acc[1], a0, a1, a2, a3, __float_as_uint(x0.y), __float_as_uint(y0.y));
                mma_tf32(acc[2], a0, a1, a2, a3, __float_as_uint(x0.z), __float_as_uint(y0.z));
                mma_tf32(acc[3], a0, a1, a2, a3, __float_as_uint(x0.w), __float_as_uint(y0.w));
                mma_tf32(acc[4], a0, a1, a2, a3, __float_as_uint(x1.x), __float_as_uint(y1.x));
                mma_tf32(acc[5], a0, a1, a2, a3, __float_as_uint(x1.y), __float_as_uint(y1.y));
                mma_tf32(acc[6], a0, a1, a2, a3, __float_as_uint(x1.z), __float_as_uint(y1.z));
                mma_tf32(acc[7], a0, a1, a2, a3, __float_as_uint(x1.w), __float_as_uint(y1.w));
            }
        }

        // ---- exact row sums, deferred V affine, COALESCED epilogue
        // (interleaved D mapping: acc[j][0] = row nq0 pixel j, acc[j][1] =
        //  row nq0 pixel 8+j, acc[j][2/3] same for row nq1; channel dd = tg)
        wsum0 += __shfl_xor_sync(0xffffffffu, wsum0, 1);
        wsum0 += __shfl_xor_sync(0xffffffffu, wsum0, 2);
        wsum1 += __shfl_xor_sync(0xffffffffu, wsum1, 1);
        wsum1 += __shfl_xor_sync(0xffffffffu, wsum1, 2);
        const float inv0 = 1.f / wsum0, inv1 = 1.f / wsum1;

        const int t0 = nq0 >> 8, y0c = (nq0 >> 4) & 15, x0c = nq0 & 15;
        const int t1 = nq1 >> 8, y1c = (nq1 >> 4) & 15, x1c = nq1 & 15;
        const size_t ob0 = ((size_t)(b * C_) + (g << 2) + tg) * S_
                         + t0 * 4096 + (y0c << 2) * 64 + (x0c << 2);
        const size_t ob1 = ((size_t)(b * C_) + (g << 2) + tg) * S_
                         + t1 * 4096 + (y1c << 2) * 64 + (x1c << 2);
#pragma unroll
        for (int half = 0; half < 2; half++) {      // j groups 0-3 / 4-7
            int jb = half << 2;
            float4 r0c = make_float4(fmaf(acc[jb][0]*inv0, aA, aB),
                                     fmaf(acc[jb+1][0]*inv0, aA, aB),
                                     fmaf(acc[jb+2][0]*inv0, aA, aB),
                                     fmaf(acc[jb+3][0]*inv0, aA, aB));
            float4 r0d = make_float4(fmaf(acc[jb][1]*inv0, aA, aB),
                                     fmaf(acc[jb+1][1]*inv0, aA, aB),
                                     fmaf(acc[jb+2][1]*inv0, aA, aB),
                                     fmaf(acc[jb+3][1]*inv0, aA, aB));
            float4 r1c = make_float4(fmaf(acc[jb][2]*inv1, aA, aB),
                                     fmaf(acc[jb+1][2]*inv1, aA, aB),
                                     fmaf(acc[jb+2][2]*inv1, aA, aB),
                                     fmaf(acc[jb+3][2]*inv1, aA, aB));
            float4 r1d = make_float4(fmaf(acc[jb][3]*inv1, aA, aB),
                                     fmaf(acc[jb+1][3]*inv1, aA, aB),
                                     fmaf(acc[jb+2][3]*inv1, aA, aB),
                                     fmaf(acc[jb+3][3]*inv1, aA, aB));
            // pixels jb..jb+3 -> sy = half; pixels 8+jb..8+jb+3 -> sy = 2+half
            *(float4*)&out[ob0 + half * 64]       = r0c;
            *(float4*)&out[ob0 + (2 + half) * 64] = r0d;
            *(float4*)&out[ob1 + half * 64]       = r1c;
            *(float4*)&out[ob1 + (2 + half) * 64] = r1d;
        }
    }
}

// ================= launch ==================================================
extern "C" void kernel_launch(void* const* d_in, const int* in_sizes, int n_in,
                              void* d_out, int out_size) {
    const float* x   = (const float*)d_in[0];
    const float* Wq  = (const float*)d_in[1];
    const float* Wk  = (const float*)d_in[2];
    const float* Wv  = (const float*)d_in[3];
    const float* gqg = (const float*)d_in[4];
    const float* gqb = (const float*)d_in[5];
    const float* gkg = (const float*)d_in[6];
    const float* gkb = (const float*)d_in[7];
    const float* gvg = (const float*)d_in[8];
    const float* gvb = (const float*)d_in[9];
    const float* rel_table = (const float*)d_in[10];
    // d_in[11] = rel_index: unused (computed analytically in-kernel)
    float* out = (float*)d_out;

    cudaFuncSetAttribute(proj_kernel, cudaFuncAttributeMaxDynamicSharedMemorySize,
                         PROJ_SMEM_BYTES);
    cudaFuncSetAttribute(attn_kernel, cudaFuncAttributeMaxDynamicSharedMemorySize,
                         ATTN_SMEM_BYTES);

    zero_kernel<<<512, 256>>>();
    proj_kernel<<<dim3(256, 2, 3), 256, PROJ_SMEM_BYTES>>>(x, Wq, Wk, Wv);
    finalize_stats<<<1, 192>>>(gqg, gqb, gkg, gkb, gvg, gvb);
    attn_kernel<<<dim3(4, 32, 2), 256, ATTN_SMEM_BYTES>>>(rel_table, out);
}

// round 12
// speedup vs baseline: 1.1122x; 1.1122x over previous
#include <cuda_runtime.h>

// Problem constants
#define B_    2
#define C_    128
#define T_    4
#define S_    16384      // T*H*W
#define NH_   32
#define N_    1024       // T*h*w = 4*16*16
#define TABSZ 6727       // (2T-1)*(2h-1)*(2w-1) = 7*31*31
#define EPS_  1e-5f
#define LOG2E_ 1.4426950408889634f

// ---------------- scratch (static device globals; no runtime alloc) -------
__device__ float g_stat[3][B_][32][2];      // groupnorm sum / sumsq partials
__device__ float g_aff[3][B_][C_][2];       // per-channel affine (a, b)
__device__ float g_qp[B_][NH_][N_][4];      // pooled Q raw sums
__device__ float g_kp[B_][NH_][N_][4];      // pooled K raw sums
__device__ float g_vp[B_][NH_][N_][64];     // RAW V, tf32-rounded, vp layout
// bf16 split components (packed pairs along the K/channel dim)
__device__ unsigned g_w0[3][128][64];       // hi comp of W, bf16x2 (c,c+1)
__device__ unsigned g_w1[3][128][64];       // residual comp
__device__ unsigned g_x0[B_][64][S_];       // hi comp of x, bf16x2 (2cp,2cp+1)
__device__ unsigned g_x1[B_][64][S_];       // residual comp

// ---------------- mma / numeric helpers ------------------------------------
__device__ __forceinline__ unsigned tf32r(float f) {
    unsigned u; asm("cvt.rna.tf32.f32 %0, %1;" : "=r"(u) : "f"(f)); return u;
}
__device__ __forceinline__ void mma_tf32(float* d, unsigned a0, unsigned a1,
                                         unsigned a2, unsigned a3,
                                         unsigned b0, unsigned b1) {
    asm("mma.sync.aligned.m16n8k8.row.col.f32.tf32.tf32.f32 "
        "{%0,%1,%2,%3}, {%4,%5,%6,%7}, {%8,%9}, {%0,%1,%2,%3};"
        : "+f"(d[0]), "+f"(d[1]), "+f"(d[2]), "+f"(d[3])
        : "r"(a0), "r"(a1), "r"(a2), "r"(a3), "r"(b0), "r"(b1));
}
__device__ __forceinline__ void mma_bf16(float* d, unsigned a0, unsigned a1,
                                         unsigned a2, unsigned a3,
                                         unsigned b0, unsigned b1) {
    asm("mma.sync.aligned.m16n8k16.row.col.f32.bf16.bf16.f32 "
        "{%0,%1,%2,%3}, {%4,%5,%6,%7}, {%8,%9}, {%0,%1,%2,%3};"
        : "+f"(d[0]), "+f"(d[1]), "+f"(d[2]), "+f"(d[3])
        : "r"(a0), "r"(a1), "r"(a2), "r"(a3), "r"(b0), "r"(b1));
}
// pack two fp32 into bf16x2: low half = lo arg, high half = hi arg
__device__ __forceinline__ unsigned pack_bf16(float lo, float hi) {
    unsigned r;
    asm("cvt.rn.bf16x2.f32 %0, %1, %2;" : "=r"(r) : "f"(hi), "f"(lo));
    return r;
}
__device__ __forceinline__ float ex2f(float x) {
    float y; asm("ex2.approx.ftz.f32 %0, %1;" : "=f"(y) : "f"(x)); return y;
}

// ---------------- cp.async helpers ----------------------------------------
__device__ __forceinline__ void cp16(void* smem, const void* g) {
    unsigned sa = (unsigned)__cvta_generic_to_shared(smem);
    asm volatile("cp.async.cg.shared.global [%0], [%1], 16;" :: "r"(sa), "l"(g));
}
__device__ __forceinline__ void cp_commit() {
    asm volatile("cp.async.commit_group;");
}
__device__ __forceinline__ void cp_wait0() {
    asm volatile("cp.async.wait_group 0;" ::: "memory");
}
__device__ __forceinline__ void cp_wait1() {
    asm volatile("cp.async.wait_group 1;" ::: "memory");
}

// ================= K0: zero accumulators ===================================
__global__ void zero_kernel() {      // <<<512, 256>>>
    int idx = blockIdx.x * 256 + threadIdx.x;       // 0..131071
    float4 z = make_float4(0.f, 0.f, 0.f, 0.f);
    if (idx < 65536) ((float4*)g_qp)[idx] = z;
    else             ((float4*)g_kp)[idx - 65536] = z;
    if (idx < 96)    ((float4*)g_stat)[idx] = z;
}

// ================= K0b: bf16 split of W ====================================
__global__ void split_w_kernel(const float* __restrict__ Wq,
                               const float* __restrict__ Wk,
                               const float* __restrict__ Wv) {  // <<<96,256>>>
    int idx = blockIdx.x * 256 + threadIdx.x;      // 0..24575
    int pr = idx >> 13, rem = idx & 8191;          // 8192 = 128*64
    int o = rem >> 6, cp = rem & 63;
    const float* Wsel = (pr == 0) ? Wq : ((pr == 1) ? Wk : Wv);
    float vlo = Wsel[o * 128 + 2 * cp];
    float vhi = Wsel[o * 128 + 2 * cp + 1];
    unsigned p0 = pack_bf16(vlo, vhi);
    float rlo = vlo - __uint_as_float(p0 << 16);
    float rhi = vhi - __uint_as_float(p0 & 0xFFFF0000u);
    g_w0[pr][o][cp] = p0;
    g_w1[pr][o][cp] = pack_bf16(rlo, rhi);
}

// ================= K0c: bf16 split of x ====================================
__global__ __launch_bounds__(256) void split_x_kernel(
    const float* __restrict__ x) {                 // <<<2048,256>>>
    int idx = blockIdx.x * 256 + threadIdx.x;      // 0..524287
    int s4 = idx & 4095, cp = (idx >> 12) & 63, b = idx >> 18;
    const float* xlo = x + ((size_t)(b * 128 + 2 * cp)) * S_ + (s4 << 2);
    float4 vl = *(const float4*)xlo;
    float4 vh = *(const float4*)(xlo + S_);
    unsigned p0[4], p1[4];
    float l[4] = {vl.x, vl.y, vl.z, vl.w};
    float h[4] = {vh.x, vh.y, vh.z, vh.w};
#pragma unroll
    for (int i = 0; i < 4; i++) {
        p0[i] = pack_bf16(l[i], h[i]);
        float rl = l[i] - __uint_as_float(p0[i] << 16);
        float rh = h[i] - __uint_as_float(p0[i] & 0xFFFF0000u);
        p1[i] = pack_bf16(rl, rh);
    }
    *(uint4*)&g_x0[b][cp][s4 << 2] = make_uint4(p0[0], p0[1], p0[2], p0[3]);
    *(uint4*)&g_x1[b][cp][s4 << 2] = make_uint4(p1[0], p1[1], p1[2], p1[3]);
}

// ================= K1: projections via bf16-split tensor GEMM ==============
// Per CTA: 128 o x 64 s tile; K=128 in 4 chunks of 32c (16 kpairs),
// double-buffered cp.async of packed bf16x2 components.
// w*x ~= w0x0 + w0x1 + w1x0  (error ~2^-16) via m16n8k16 bf16 MMA.
// Smem: Ws[o:128][comp:2][kp:16] pitch 36; Xs[comp:2][cp:16][s] pitch 72.
#define WSTG (128 * 36)               // 4608 uints / stage
#define XSTG (2 * 16 * 72)            // 2304 uints / stage
#define SB_OFF (2 * WSTG + 2 * XSTG)  // 13824
#define PROJ_SMEM_FLOATS (SB_OFF + 512)
#define PROJ_SMEM_BYTES  (PROJ_SMEM_FLOATS * 4)

__global__ __launch_bounds__(256) void proj_kernel() {
    extern __shared__ float sm[];
    unsigned* Ws = (unsigned*)sm;
    unsigned* Xs = (unsigned*)sm + 2 * WSTG;
    float* sbuf  = sm + SB_OFF;

    const int pr  = blockIdx.z;
    const int b   = blockIdx.y;
    const int s_t = blockIdx.x << 6;
    const int tid = threadIdx.x;

    auto issue = [&](int kc, int st) {
        unsigned* wd = Ws + st * WSTG;
        unsigned* xd = Xs + st * XSTG;
#pragma unroll
        for (int j = 0; j < 4; j++) {          // W: 4096 uints = 1024 cp16
            int e = tid + 256 * j;
            int o = e >> 3, grp = e & 7;
            int comp = grp >> 2, seg = grp & 3;
            const unsigned* src = comp ? &g_w1[pr][o][kc * 16 + seg * 4]
                                       : &g_w0[pr][o][kc * 16 + seg * 4];
            cp16(wd + o * 36 + comp * 16 + seg * 4, src);
        }
#pragma unroll
        for (int j = 0; j < 2; j++) {          // X: 2048 uints = 512 cp16
            int e = tid + 256 * j;
            int comp = e >> 8, r = e & 255;
            int cp = r >> 4, seg = r & 15;
            const unsigned* src = comp ? &g_x1[b][kc * 16 + cp][s_t + seg * 4]
                                       : &g_x0[b][kc * 16 + cp][s_t + seg * 4];
            cp16(xd + comp * 1152 + cp * 72 + seg * 4, src);
        }
        cp_commit();
    };

    const int warp = tid >> 5, lane = tid & 31;
    const int gid = lane >> 2, tg = lane & 3;
    const int ow = warp >> 1, sw = warp & 1;
    const int o0 = ow << 5;
    const int sbase = sw << 5;

    float acc[2][4][4];
#pragma unroll
    for (int mb = 0; mb < 2; mb++)
#pragma unroll
        for (int nb = 0; nb < 4; nb++)
#pragma unroll
            for (int i = 0; i < 4; i++) acc[mb][nb][i] = 0.f;

    issue(0, 0);
    for (int kc = 0; kc < 4; kc++) {
        cp_wait0();
        __syncthreads();
        if (kc < 3) issue(kc + 1, (kc + 1) & 1);
        const unsigned* Wb = Ws + (kc & 1) * WSTG;
        const unsigned* Xb = Xs + (kc & 1) * XSTG;

#pragma unroll
        for (int ks2 = 0; ks2 < 2; ks2++) {
            const int kb = ks2 << 3;
            // B frags: b0 = kpair kb+tg, b1 = kpair kb+tg+4, col gid
            unsigned bx0[4][2], bx1[4][2];
#pragma unroll
            for (int nb = 0; nb < 4; nb++) {
                const unsigned* xc0 = Xb + (kb + tg) * 72 + sbase + nb * 8 + gid;
                bx0[nb][0] = xc0[0];
                bx0[nb][1] = xc0[4 * 72];
                const unsigned* xc1 = xc0 + 1152;
                bx1[nb][0] = xc1[0];
                bx1[nb][1] = xc1[4 * 72];
            }
#pragma unroll
            for (int mb = 0; mb < 2; mb++) {
                const unsigned* w0p = Wb + (o0 + mb * 16 + gid) * 36 + kb + tg;
                const unsigned* w1p = w0p + 16;
                unsigned a00 = w0p[0], a01 = w0p[8 * 36];
                unsigned a02 = w0p[4], a03 = w0p[8 * 36 + 4];
                unsigned a10 = w1p[0], a11 = w1p[8 * 36];
                unsigned a12 = w1p[4], a13 = w1p[8 * 36 + 4];
#pragma unroll
                for (int nb = 0; nb < 4; nb++) {
                    mma_bf16(acc[mb][nb], a00, a01, a02, a03, bx0[nb][0], bx0[nb][1]);
                    mma_bf16(acc[mb][nb], a00, a01, a02, a03, bx1[nb][0], bx1[nb][1]);
                    mma_bf16(acc[mb][nb], a10, a11, a12, a13, bx0[nb][0], bx0[nb][1]);
                }
            }
        }
        __syncthreads();
    }

    // ---- epilogue coordinates
    const int t  = s_t >> 12;
    const int hh = (s_t >> 6) & 63;
    const int y  = hh >> 2, sy = hh & 3;
    const int nbase = t * 256 + (y << 4);

    if (pr < 2) {
        float* dstp = (pr == 0) ? &g_qp[0][0][0][0] : &g_kp[0][0][0][0];
#pragma unroll
        for (int mb = 0; mb < 2; mb++) {
            const int cA = o0 + mb * 16 + gid, cB = cA + 8;
#pragma unroll
            for (int nb = 0; nb < 4; nb++) {
                float sA = acc[mb][nb][0] + acc[mb][nb][1];
                float sB = acc[mb][nb][2] + acc[mb][nb][3];
                sA += __shfl_xor_sync(0xffffffffu, sA, 1);
                sB += __shfl_xor_sync(0xffffffffu, sB, 1);
                if ((tg & 1) == 0) {
                    int n = nbase + (sw << 3) + (nb << 1) + (tg >> 1);
                    atomicAdd(dstp + (((size_t)(b * 32 + (cA >> 2)) * 1024 + n) << 2)
                                   + (cA & 3), sA);
                    atomicAdd(dstp + (((size_t)(b * 32 + (cB >> 2)) * 1024 + n) << 2)
                                   + (cB & 3), sB);
                }
            }
        }
    } else {
        float* Zs = sm;                      // 128 x 72 floats = 9216 < SB_OFF
#pragma unroll
        for (int mb = 0; mb < 2; mb++) {
            const int r = o0 + mb * 16 + gid;
#pragma unroll
            for (int nb = 0; nb < 4; nb++) {
                int col = sbase + nb * 8 + (tg << 1);
                *(float2*)&Zs[r * 72 + col]       = make_float2(acc[mb][nb][0], acc[mb][nb][1]);
                *(float2*)&Zs[(r + 8) * 72 + col] = make_float2(acc[mb][nb][2], acc[mb][nb][3]);
            }
        }
    }

    // ---- fused GroupNorm partial stats
#pragma unroll
    for (int mb = 0; mb < 2; mb++)
#pragma unroll
        for (int hi = 0; hi < 2; hi++) {
            float s = 0.f, s2 = 0.f;
#pragma unroll
            for (int nb = 0; nb < 4; nb++) {
                float v0 = acc[mb][nb][hi * 2 + 0];
                float v1 = acc[mb][nb][hi * 2 + 1];
                s += v0 + v1;
                s2 = fmaf(v0, v0, s2); s2 = fmaf(v1, v1, s2);
            }
            s  += __shfl_xor_sync(0xffffffffu, s, 1);
            s  += __shfl_xor_sync(0xffffffffu, s, 2);
            s2 += __shfl_xor_sync(0xffffffffu, s2, 1);
            s2 += __shfl_xor_sync(0xffffffffu, s2, 2);
            if (tg == 0) {
                int idx = (((warp << 3) | gid) << 3) | (mb << 2) | (hi << 1);
                sbuf[idx]     = s;
                sbuf[idx + 1] = s2;
            }
        }
    __syncthreads();

    if (pr == 2) {
        const float* Zs = sm;
#pragma unroll
        for (int j = 0; j < 8; j++) {
            int e = tid + (j << 8);
            int c = e >> 4, xq = e & 15;
            float4 v = *(const float4*)&Zs[c * 72 + (xq << 2)];
            float4 r = make_float4(
                __uint_as_float(tf32r(v.x)), __uint_as_float(tf32r(v.y)),
                __uint_as_float(tf32r(v.z)), __uint_as_float(tf32r(v.w)));
            *(float4*)&g_vp[b][c >> 2][nbase + xq][((c & 3) << 4) + (sy << 2)] = r;
        }
    }
    if (tid < 64) {
        int grp = tid >> 1, v = tid & 1;
        float tot = 0.f;
#pragma unroll
        for (int ci = 0; ci < 4; ci++) {
            int ch = (grp << 2) + ci;
            int cow = ch >> 5, r = ch & 31;
            int cmb = r >> 4, chi = (r >> 3) & 1, cgid = r & 7;
#pragma unroll
            for (int csw = 0; csw < 2; csw++) {
                int w2 = (cow << 1) | csw;
                tot += sbuf[(((w2 << 3) | cgid) << 3) | (cmb << 2) | (chi << 1) | v];
            }
        }
        atomicAdd(&g_stat[pr][b][grp][v], tot);
    }
}

// ================= K2: finalize stats -> per-channel affine ================
__global__ void finalize_stats(
    const float* __restrict__ gqg, const float* __restrict__ gqb,
    const float* __restrict__ gkg, const float* __restrict__ gkb,
    const float* __restrict__ gvg, const float* __restrict__ gvb) {   // <<<1,192>>>
    int i = threadIdx.x;
    int pr = i >> 6, r = i & 63, b = r >> 5, grp = r & 31;
    float s  = g_stat[pr][b][grp][0];
    float s2 = g_stat[pr][b][grp][1];
    float mean = s * (1.f / 65536.f);
    float var  = s2 * (1.f / 65536.f) - mean * mean;
    float rstd = rsqrtf(var + EPS_);
    const float* ga = (pr == 0) ? gqg : ((pr == 1) ? gkg : gvg);
    const float* be = (pr == 0) ? gqb : ((pr == 1) ? gkb : gvb);
#pragma unroll
    for (int d = 0; d < 4; d++) {
        int c = (grp << 2) + d;
        float a = rstd * ga[c];
        g_aff[pr][b][c][0] = a;
        g_aff[pr][b][c][1] = be[c] - mean * a;
    }
}

// ================= K3: fused tensor-core patch attention (round-9 proven) ==
#define VSP_    72
#define VS_BUF  (64 * VSP_)                 // 4608 floats per stage
#define SM_TAB  0
#define SM_K    6728                        // 1024 float4
#define SM_KC   (SM_K + 4096)               // 1024 ints
#define SM_VS   (SM_KC + 1024)              // 3 * 4608
#define SM_RED  (SM_VS + 3 * VS_BUF)        // 16
#define ATTN_SMEM_FLOATS (SM_RED + 16)
#define ATTN_SMEM_BYTES (ATTN_SMEM_FLOATS * 4)

__global__ __launch_bounds__(256, 2) void attn_kernel(
    const float* __restrict__ rel_table, float* __restrict__ out) {
    extern __shared__ float sm[];
    float*  tab  = sm + SM_TAB;
    float4* ks4  = (float4*)(sm + SM_K);
    int*    kc   = (int*)(sm + SM_KC);
    float*  vsb0 = sm + SM_VS;
    float*  red  = sm + SM_RED;

    const int b = blockIdx.z, g = blockIdx.y;
    const int n0 = blockIdx.x << 7;
    const int tid = threadIdx.x;

    // ---- kick off V chunks 0 and 1 immediately
#pragma unroll
    for (int st = 0; st < 2; st++) {
        const float* vsrc = &g_vp[b][g][st << 6][0];
        float* vdst = vsb0 + st * VS_BUF;
#pragma unroll
        for (int j = 0; j < 4; j++) {
            int idx = tid + 256 * j;
            int row = idx >> 4, seg = idx & 15;
            cp16(vdst + row * VSP_ + seg * 4, vsrc + row * 64 + seg * 4);
        }
        cp_commit();
    }

    // ---- load bias table (scaled by log2e), normalized K; reduce maxima
    float tmax = -1e30f;
    for (int i = tid; i < TABSZ; i += 256) {
        float v = rel_table[g * TABSZ + i] * LOG2E_;
        tab[i] = v;
        tmax = fmaxf(tmax, v);
    }
    const float* afk = &g_aff[1][b][g << 2][0];     // [a0,b0,a1,b1,a2,b2,a3,b3]
    float4 afk0 = *(const float4*)afk;
    float4 afk1 = *(const float4*)(afk + 4);
    float knmax = 0.f;
    for (int i = tid; i < 1024; i += 256) {
        float4 kr = *(const float4*)&g_kp[b][g][i][0];
        float4 kk;
        kk.x = fmaf(kr.x * 0.0625f, afk0.x, afk0.y);
        kk.y = fmaf(kr.y * 0.0625f, afk0.z, afk0.w);
        kk.z = fmaf(kr.z * 0.0625f, afk1.x, afk1.y);
        kk.w = fmaf(kr.w * 0.0625f, afk1.z, afk1.w);
        ks4[i] = kk;
        kc[i]  = 961 * (i >> 8) + 31 * ((i >> 4) & 15) + (i & 15);
        float nn = fmaf(kk.x, kk.x, fmaf(kk.y, kk.y, fmaf(kk.z, kk.z, kk.w * kk.w)));
        knmax = fmaxf(knmax, nn);
    }
#pragma unroll
    for (int o = 16; o; o >>= 1) {
        tmax  = fmaxf(tmax,  __shfl_xor_sync(0xffffffffu, tmax,  o));
        knmax = fmaxf(knmax, __shfl_xor_sync(0xffffffffu, knmax, o));
    }
    int w = tid >> 5;
    if ((tid & 31) == 0) { red[w] = tmax; red[8 + w] = knmax; }
    __syncthreads();
    tmax = red[0]; knmax = red[8];
#pragma unroll
    for (int i = 1; i < 8; i++) {
        tmax = fmaxf(tmax, red[i]); knmax = fmaxf(knmax, red[8 + i]);
    }
    const float kn = sqrtf(knmax);

    // ---- per-thread identity; q: normalize then scale to log2 domain
    const int warp = tid >> 5, lane = tid & 31;
    const int gid = lane >> 2, tg = lane & 3;
    const int r0 = (warp << 4) + gid;
    const int nq0 = n0 + r0, nq1 = nq0 + 8;
    const float* afq = &g_aff[0][b][g << 2][0];
    float4 afq0 = *(const float4*)afq;
    float4 afq1 = *(const float4*)(afq + 4);
    const float HS = 0.5f * LOG2E_;
    float4 qr0 = *(const float4*)&g_qp[b][g][nq0][0];
    float4 qr1 = *(const float4*)&g_qp[b][g][nq1][0];
    float4 q0, q1;
    q0.x = fmaf(qr0.x * 0.0625f, afq0.x, afq0.y) * HS;
    q0.y = fmaf(qr0.y * 0.0625f, afq0.z, afq0.w) * HS;
    q0.z = fmaf(qr0.z * 0.0625f, afq1.x, afq1.y) * HS;
    q0.w = fmaf(qr0.w * 0.0625f, afq1.z, afq1.w) * HS;
    q1.x = fmaf(qr1.x * 0.0625f, afq0.x, afq0.y) * HS;
    q1.y = fmaf(qr1.y * 0.0625f, afq0.z, afq0.w) * HS;
    q1.z = fmaf(qr1.z * 0.0625f, afq1.x, afq1.y) * HS;
    q1.w = fmaf(qr1.w * 0.0625f, afq1.z, afq1.w) * HS;
    const float qq0 = fmaf(q0.x, q0.x, fmaf(q0.y, q0.y, fmaf(q0.z, q0.z, q0.w * q0.w)));
    const float qq1 = fmaf(q1.x, q1.x, fmaf(q1.y, q1.y, fmaf(q1.z, q1.z, q1.w * q1.w)));
    const float bnd0 = fmaf(sqrtf(qq0), kn, tmax);
    const float bnd1 = fmaf(sqrtf(qq1), kn, tmax);
    const int cn0 = 961 * (nq0 >> 8) + 31 * ((nq0 >> 4) & 15) + (nq0 & 15) + 3363;
    const int cn1 = 961 * (nq1 >> 8) + 31 * ((nq1 >> 4) & 15) + (nq1 & 15) + 3363;

    float acc[8][4];
#pragma unroll
    for (int j = 0; j < 8; j++)
#pragma unroll
        for (int i = 0; i < 4; i++) acc[j][i] = 0.f;
    float wsum0 = 0.f, wsum1 = 0.f;

    // ---- main loop: 16 chunks of 64 keys, 3-stage cp.async ring
    for (int mc = 0; mc < 16; mc++) {
        if (mc < 15) cp_wait1(); else cp_wait0();
        __syncthreads();
        if (mc + 2 < 16) {
            const float* vsrc = &g_vp[b][g][(mc + 2) << 6][0];
            float* vdst = vsb0 + ((mc + 2) % 3) * VS_BUF;
#pragma unroll
            for (int j = 0; j < 4; j++) {
                int idx = tid + 256 * j;
                int row = idx >> 4, seg = idx & 15;
                cp16(vdst + row * VSP_ + seg * 4, vsrc + row * 64 + seg * 4);
            }
            cp_commit();
        }
        const float* vsb = vsb0 + (mc % 3) * VS_BUF;
        const int m0 = mc << 6;

#pragma unroll
        for (int sub = 0; sub < 8; sub++) {
            const int mk = m0 + (sub << 3);
            float4 k0 = ks4[mk + tg];
            float4 k1 = ks4[mk + tg + 4];
            int c0i = kc[mk + tg], c1i = kc[mk + tg + 4];

            float d00 = fmaf(q0.x, k0.x, fmaf(q0.y, k0.y, fmaf(q0.z, k0.z, q0.w * k0.w)));
            float d01 = fmaf(q0.x, k1.x, fmaf(q0.y, k1.y, fmaf(q0.z, k1.z, q0.w * k1.w)));
            float d10 = fmaf(q1.x, k0.x, fmaf(q1.y, k0.y, fmaf(q1.z, k0.z, q1.w * k0.w)));
            float d11 = fmaf(q1.x, k1.x, fmaf(q1.y, k1.y, fmaf(q1.z, k1.z, q1.w * k1.w)));

            float w00 = ex2f(d00 + tab[cn0 - c0i] - bnd0);
            float w01 = ex2f(d01 + tab[cn0 - c1i] - bnd0);
            float w10 = ex2f(d10 + tab[cn1 - c0i] - bnd1);
            float w11 = ex2f(d11 + tab[cn1 - c1i] - bnd1);
            wsum0 += w00 + w01;
            wsum1 += w10 + w11;

            unsigned a0 = __float_as_uint(w00), a1 = __float_as_uint(w10);
            unsigned a2 = __float_as_uint(w01), a3 = __float_as_uint(w11);

            // scalar B-frag loads: banks 8*tg + gid -> perfect conflict-free
            const float* vr0 = vsb + ((sub << 3) + tg) * VSP_ + gid;
            const float* vr1 = vr0 + 4 * VSP_;
#pragma unroll
            for (int j = 0; j < 8; j++) {
                unsigned b0 = __float_as_uint(vr0[8 * j]);
                unsigned b1 = __float_as_uint(vr1[8 * j]);
                mma_tf32(acc[j], a0, a1, a2, a3, b0, b1);
            }
        }
    }

    // ---- exact row sums, deferred V affine, epilogue
    wsum0 += __shfl_xor_sync(0xffffffffu, wsum0, 1);
    wsum0 += __shfl_xor_sync(0xffffffffu, wsum0, 2);
    wsum1 += __shfl_xor_sync(0xffffffffu, wsum1, 1);
    wsum1 += __shfl_xor_sync(0xffffffffu, wsum1, 2);
    const float inv0 = 1.f / wsum0, inv1 = 1.f / wsum1;

    float avA[4], avB[4];
#pragma unroll
    for (int dd = 0; dd < 4; dd++) {
        avA[dd] = g_aff[2][b][(g << 2) + dd][0];
        avB[dd] = g_aff[2][b][(g << 2) + dd][1];
    }

    const int t0 = nq0 >> 8, y0 = (nq0 >> 4) & 15, x0 = nq0 & 15;
    const int t1 = nq1 >> 8, y1 = (nq1 >> 4) & 15, x1 = nq1 & 15;
    const size_t ob0 = ((size_t)(b * C_) + (g << 2)) * S_
                     + t0 * 4096 + (y0 << 2) * 64 + (x0 << 2);
    const size_t ob1 = ((size_t)(b * C_) + (g << 2)) * S_
                     + t1 * 4096 + (y1 << 2) * 64 + (x1 << 2);
#pragma unroll
    for (int j = 0; j < 8; j++) {
        int col = 8 * j + 2 * tg;
        int dd = col >> 4, p = col & 15;
        int sy = p >> 2, sx = p & 3;
        size_t off = (size_t)dd * S_ + sy * 64 + sx;
        *(float2*)&out[ob0 + off] = make_float2(
            fmaf(acc[j][0] * inv0, avA[dd], avB[dd]),
            fmaf(acc[j][1] * inv0, avA[dd], avB[dd]));
        *(float2*)&out[ob1 + off] = make_float2(
            fmaf(acc[j][2] * inv1, avA[dd], avB[dd]),
            fmaf(acc[j][3] * inv1, avA[dd], avB[dd]));
    }
}

// ================= launch ==================================================
extern "C" void kernel_launch(void* const* d_in, const int* in_sizes, int n_in,
                              void* d_out, int out_size) {
    const float* x   = (const float*)d_in[0];
    const float* Wq  = (const float*)d_in[1];
    const float* Wk  = (const float*)d_in[2];
    const float* Wv  = (const float*)d_in[3];
    const float* gqg = (const float*)d_in[4];
    const float* gqb = (const float*)d_in[5];
    const float* gkg = (const float*)d_in[6];
    const float* gkb = (const float*)d_in[7];
    const float* gvg = (const float*)d_in[8];
    const float* gvb = (const float*)d_in[9];
    const float* rel_table = (const float*)d_in[10];
    // d_in[11] = rel_index: unused (computed analytically in-kernel)
    float* out = (float*)d_out;

    cudaFuncSetAttribute(proj_kernel, cudaFuncAttributeMaxDynamicSharedMemorySize,
                         PROJ_SMEM_BYTES);
    cudaFuncSetAttribute(attn_kernel, cudaFuncAttributeMaxDynamicSharedMemorySize,
                         ATTN_SMEM_BYTES);

    zero_kernel<<<512, 256>>>();
    split_w_kernel<<<96, 256>>>(Wq, Wk, Wv);
    split_x_kernel<<<2048, 256>>>(x);
    proj_kernel<<<dim3(256, 2, 3), 256, PROJ_SMEM_BYTES>>>();
    finalize_stats<<<1, 192>>>(gqg, gqb, gkg, gkb, gvg, gvb);
    attn_kernel<<<dim3(8, 32, 2), 256, ATTN_SMEM_BYTES>>>(rel_table, out);
}